// round 5
// baseline (speedup 1.0000x reference)
#include <cuda_runtime.h>
#include <cstdint>

#define NUM_EXPERTS 8
#define TOPK 2
#define BATCH 2048
#define HIDDEN 1024
#define FFN 4096
#define PAIRS (BATCH * TOPK)          // 4096
#define BM 128
#define BN 128
#define BKT 16
#define ROWS_CAP (PAIRS + NUM_EXPERTS * BM)   // 5120 (worst-case padding)
#define MAX_MT (PAIRS / BM + NUM_EXPERTS)     // 40 M-tiles max

// ---------------- scratch (static device globals; no allocation) ----------------
__device__ float g_h1[(size_t)ROWS_CAP * FFN];     // 80 MB intermediate silu(x@w1)
__device__ float g_y[(size_t)ROWS_CAP * HIDDEN];   // 20 MB per-pair outputs (rw applied)
__device__ int   g_row_token[ROWS_CAP];
__device__ float g_row_rw[ROWS_CAP];
__device__ int   g_rowof[PAIRS];
__device__ int   g_tile_e[MAX_MT];
__device__ int   g_tile_r0[MAX_MT];
__device__ int   g_ntiles;
// input-disambiguation flag (set by route_kernel probe, read by gemm kernels)
__device__ int   g_sel_w1;   // 1 -> big0 is w1, else big1 is w1

// ---------------- helpers ----------------
__device__ __forceinline__ float to_tf32(float x) {
    asm("cvt.rna.tf32.f32 %0, %1;" : "=f"(x) : "f"(x));
    return x;
}

__device__ __forceinline__ void mma_tf32(float c[4],
                                         uint32_t a0, uint32_t a1, uint32_t a2, uint32_t a3,
                                         uint32_t b0, uint32_t b1) {
    asm volatile(
        "mma.sync.aligned.m16n8k8.row.col.f32.tf32.tf32.f32 "
        "{%0,%1,%2,%3},{%4,%5,%6,%7},{%8,%9},{%0,%1,%2,%3};\n"
        : "+f"(c[0]), "+f"(c[1]), "+f"(c[2]), "+f"(c[3])
        : "r"(a0), "r"(a1), "r"(a2), "r"(a3), "r"(b0), "r"(b1));
}

__device__ __forceinline__ float silu(float v) {
    return v * (1.0f / (1.0f + __expf(-v)));
}

// ---------------- routing: probe inputs + counting sort by expert ----------------
// sm0/sm1: the two 4096-element buffers (one is expert_indices, one routing_weights)
// big0/big1: the two 33.5M-element buffers (one is w1, one w2)
__global__ void route_kernel(const void* __restrict__ sm0,
                             const void* __restrict__ sm1,
                             const float* __restrict__ big0,
                             const float* __restrict__ big1) {
    __shared__ int cnt[NUM_EXPERTS];
    __shared__ int off[NUM_EXPERTS];
    __shared__ int cur[NUM_EXPERTS];
    __shared__ int s_sel_idx;   // 1 -> sm0 is indices
    __shared__ int s_idx64;     // 1 -> indices are int64
    __shared__ float s_ss0, s_ss1;
    int t = threadIdx.x;

    // ---- probe 1: which small buffer is expert_indices, and its width ----
    // An int64/int32 index buffer has every value in [0,8). Float bit patterns
    // of U[0,1) values (exponent field 0x3Exx..0x3F7F) can never read as such.
    if (t == 0) {
        int sel = 0, w64 = 1;
        {   // sm0 as int64
            const long long* q = (const long long*)sm0;
            bool ok = true;
            for (int i = 0; i < 32; i++) { long long v = q[i]; if (v < 0 || v >= NUM_EXPERTS) ok = false; }
            if (ok) { sel = 1; w64 = 1; goto done; }
        }
        {   // sm0 as int32
            const int* q = (const int*)sm0;
            bool ok = true;
            for (int i = 0; i < 32; i++) { int v = q[i]; if (v < 0 || v >= NUM_EXPERTS) ok = false; }
            if (ok) { sel = 1; w64 = 0; goto done; }
        }
        {   // sm1 as int64
            const long long* q = (const long long*)sm1;
            bool ok = true;
            for (int i = 0; i < 32; i++) { long long v = q[i]; if (v < 0 || v >= NUM_EXPERTS) ok = false; }
            if (ok) { sel = 0; w64 = 1; goto done; }
        }
        sel = 0; w64 = 0;   // fall back: sm1 is indices, int32
    done:
        s_sel_idx = sel; s_idx64 = w64;
        s_ss0 = 0.f; s_ss1 = 0.f;
    }
    if (t < NUM_EXPERTS) cnt[t] = 0;
    __syncthreads();

    // ---- probe 2: which big buffer is w1 (var 1/1024) vs w2 (var 1/4096) ----
    // 32768 samples: E[ss] = 32 vs 8, separation > 30 sigma.
    {
        float a0 = 0.f, a1 = 0.f;
        for (int i = t; i < 32768; i += blockDim.x) {
            float v0 = big0[i]; a0 += v0 * v0;
            float v1 = big1[i]; a1 += v1 * v1;
        }
        atomicAdd(&s_ss0, a0);
        atomicAdd(&s_ss1, a1);
    }
    __syncthreads();
    if (t == 0) g_sel_w1 = (s_ss0 > s_ss1) ? 1 : 0;

    const void*  idxp = s_sel_idx ? sm0 : sm1;
    const float* rw   = s_sel_idx ? (const float*)sm1 : (const float*)sm0;
    int idx64 = s_idx64;

    // ---- counting sort by expert into 128-row-aligned segments ----
    for (int p = t; p < PAIRS; p += blockDim.x) {
        int e = idx64 ? (int)((const long long*)idxp)[p] : ((const int*)idxp)[p];
        atomicAdd(&cnt[e], 1);
    }
    for (int r = t; r < ROWS_CAP; r += blockDim.x)
        g_row_token[r] = -1;
    __syncthreads();
    if (t == 0) {
        int o = 0, nt = 0;
        for (int e = 0; e < NUM_EXPERTS; e++) {
            off[e] = o; cur[e] = 0;
            int ntile = (cnt[e] + BM - 1) / BM;
            for (int i = 0; i < ntile; i++) {
                g_tile_e[nt] = e;
                g_tile_r0[nt] = o + i * BM;
                nt++;
            }
            o += ntile * BM;
        }
        g_ntiles = nt;
    }
    __syncthreads();
    for (int p = t; p < PAIRS; p += blockDim.x) {
        int e = idx64 ? (int)((const long long*)idxp)[p] : ((const int*)idxp)[p];
        int r = off[e] + atomicAdd(&cur[e], 1);
        g_row_token[r] = p >> 1;       // token id
        g_row_rw[r] = rw[p];
        g_rowof[p] = r;
    }
}

// ---------------- GEMM1: h1 = silu( gather(X) @ w1[e] ), M-tiles x (FFN/BN) ----------------
__global__ __launch_bounds__(256, 2) void gemm1_kernel(const float* __restrict__ x,
                                                       const float* __restrict__ big0,
                                                       const float* __restrict__ big1) {
    int mt = blockIdx.x;
    if (mt >= g_ntiles) return;
    const float* w1 = g_sel_w1 ? big0 : big1;
    int e  = g_tile_e[mt];
    int r0 = g_tile_r0[mt];
    int n0 = blockIdx.y * BN;

    __shared__ __align__(16) float As[BM][20];   // [row][k], pad 20 -> conflict-free frag loads
    __shared__ float Bs[BN][20];                 // [n][k] (transposed on load)
    __shared__ int stok[BM];

    int t = threadIdx.x;
    for (int i = t; i < BM; i += 256) stok[i] = g_row_token[r0 + i];
    __syncthreads();

    int lane = t & 31, warp = t >> 5;
    int wm = warp >> 2, wn = warp & 3;   // 2 x 4 warp grid; warp tile 64x32
    int g = lane >> 2, tg = lane & 3;

    float acc[4][4][4];
#pragma unroll
    for (int mi = 0; mi < 4; mi++)
#pragma unroll
        for (int ni = 0; ni < 4; ni++)
#pragma unroll
            for (int c = 0; c < 4; c++) acc[mi][ni][c] = 0.0f;

    const float* wB = w1 + (size_t)e * HIDDEN * FFN;

    for (int k0 = 0; k0 < HIDDEN; k0 += BKT) {
        // A tile: 128 rows x 16 k (gathered, zero-fill padded rows)
#pragma unroll
        for (int j = 0; j < 2; j++) {
            int q = t + j * 256;          // 0..511
            int row = q >> 2, kv = (q & 3) * 4;
            float4 v = make_float4(0.f, 0.f, 0.f, 0.f);
            int tok = stok[row];
            if (tok >= 0)
                v = *(const float4*)(x + (size_t)tok * HIDDEN + k0 + kv);
            v.x = to_tf32(v.x); v.y = to_tf32(v.y); v.z = to_tf32(v.z); v.w = to_tf32(v.w);
            *(float4*)&As[row][kv] = v;
        }
        // B tile: 16 k x 128 n, transpose into Bs[n][k]
#pragma unroll
        for (int j = 0; j < 2; j++) {
            int q = t + j * 256;
            int k = q >> 5, nv = (q & 31) * 4;
            float4 v = *(const float4*)(wB + (size_t)(k0 + k) * FFN + n0 + nv);
            Bs[nv + 0][k] = to_tf32(v.x);
            Bs[nv + 1][k] = to_tf32(v.y);
            Bs[nv + 2][k] = to_tf32(v.z);
            Bs[nv + 3][k] = to_tf32(v.w);
        }
        __syncthreads();

#pragma unroll
        for (int kk = 0; kk < BKT; kk += 8) {
            uint32_t a[4][4], b[4][2];
#pragma unroll
            for (int mi = 0; mi < 4; mi++) {
                int r = wm * 64 + mi * 16;
                a[mi][0] = __float_as_uint(As[r + g][kk + tg]);
                a[mi][1] = __float_as_uint(As[r + g + 8][kk + tg]);
                a[mi][2] = __float_as_uint(As[r + g][kk + tg + 4]);
                a[mi][3] = __float_as_uint(As[r + g + 8][kk + tg + 4]);
            }
#pragma unroll
            for (int ni = 0; ni < 4; ni++) {
                int n = wn * 32 + ni * 8;
                b[ni][0] = __float_as_uint(Bs[n + g][kk + tg]);
                b[ni][1] = __float_as_uint(Bs[n + g][kk + tg + 4]);
            }
#pragma unroll
            for (int mi = 0; mi < 4; mi++)
#pragma unroll
                for (int ni = 0; ni < 4; ni++)
                    mma_tf32(acc[mi][ni], a[mi][0], a[mi][1], a[mi][2], a[mi][3],
                             b[ni][0], b[ni][1]);
        }
        __syncthreads();
    }

    // epilogue: silu, store to g_h1 (padded rows get 0 -> harmless downstream)
#pragma unroll
    for (int mi = 0; mi < 4; mi++) {
#pragma unroll
        for (int ni = 0; ni < 4; ni++) {
            int r = r0 + wm * 64 + mi * 16 + g;
            int c = n0 + wn * 32 + ni * 8 + 2 * tg;
            float2 v01 = make_float2(silu(acc[mi][ni][0]), silu(acc[mi][ni][1]));
            float2 v23 = make_float2(silu(acc[mi][ni][2]), silu(acc[mi][ni][3]));
            *(float2*)(g_h1 + (size_t)r * FFN + c) = v01;
            *(float2*)(g_h1 + (size_t)(r + 8) * FFN + c) = v23;
        }
    }
}

// ---------------- GEMM2: y = (h1 @ w2[e]) * rw, M-tiles x (HIDDEN/BN) ----------------
__global__ __launch_bounds__(256, 2) void gemm2_kernel(const float* __restrict__ big0,
                                                       const float* __restrict__ big1) {
    int mt = blockIdx.x;
    if (mt >= g_ntiles) return;
    const float* w2 = g_sel_w1 ? big1 : big0;
    int e  = g_tile_e[mt];
    int r0 = g_tile_r0[mt];
    int n0 = blockIdx.y * BN;

    __shared__ __align__(16) float As[BM][20];
    __shared__ float Bs[BN][20];
    __shared__ float srw[BM];

    int t = threadIdx.x;
    for (int i = t; i < BM; i += 256) srw[i] = g_row_rw[r0 + i];
    __syncthreads();

    int lane = t & 31, warp = t >> 5;
    int wm = warp >> 2, wn = warp & 3;
    int g = lane >> 2, tg = lane & 3;

    float acc[4][4][4];
#pragma unroll
    for (int mi = 0; mi < 4; mi++)
#pragma unroll
        for (int ni = 0; ni < 4; ni++)
#pragma unroll
            for (int c = 0; c < 4; c++) acc[mi][ni][c] = 0.0f;

    const float* wB = w2 + (size_t)e * FFN * HIDDEN;

    for (int k0 = 0; k0 < FFN; k0 += BKT) {
#pragma unroll
        for (int j = 0; j < 2; j++) {
            int q = t + j * 256;
            int row = q >> 2, kv = (q & 3) * 4;
            float4 v = *(const float4*)(g_h1 + (size_t)(r0 + row) * FFN + k0 + kv);
            v.x = to_tf32(v.x); v.y = to_tf32(v.y); v.z = to_tf32(v.z); v.w = to_tf32(v.w);
            *(float4*)&As[row][kv] = v;
        }
#pragma unroll
        for (int j = 0; j < 2; j++) {
            int q = t + j * 256;
            int k = q >> 5, nv = (q & 31) * 4;
            float4 v = *(const float4*)(wB + (size_t)(k0 + k) * HIDDEN + n0 + nv);
            Bs[nv + 0][k] = to_tf32(v.x);
            Bs[nv + 1][k] = to_tf32(v.y);
            Bs[nv + 2][k] = to_tf32(v.z);
            Bs[nv + 3][k] = to_tf32(v.w);
        }
        __syncthreads();

#pragma unroll
        for (int kk = 0; kk < BKT; kk += 8) {
            uint32_t a[4][4], b[4][2];
#pragma unroll
            for (int mi = 0; mi < 4; mi++) {
                int r = wm * 64 + mi * 16;
                a[mi][0] = __float_as_uint(As[r + g][kk + tg]);
                a[mi][1] = __float_as_uint(As[r + g + 8][kk + tg]);
                a[mi][2] = __float_as_uint(As[r + g][kk + tg + 4]);
                a[mi][3] = __float_as_uint(As[r + g + 8][kk + tg + 4]);
            }
#pragma unroll
            for (int ni = 0; ni < 4; ni++) {
                int n = wn * 32 + ni * 8;
                b[ni][0] = __float_as_uint(Bs[n + g][kk + tg]);
                b[ni][1] = __float_as_uint(Bs[n + g][kk + tg + 4]);
            }
#pragma unroll
            for (int mi = 0; mi < 4; mi++)
#pragma unroll
                for (int ni = 0; ni < 4; ni++)
                    mma_tf32(acc[mi][ni], a[mi][0], a[mi][1], a[mi][2], a[mi][3],
                             b[ni][0], b[ni][1]);
        }
        __syncthreads();
    }

    // epilogue: scale by routing weight, store per-pair output rows
#pragma unroll
    for (int mi = 0; mi < 4; mi++) {
        int lr = wm * 64 + mi * 16 + g;
        float w0 = srw[lr];
        float w1r = srw[lr + 8];
#pragma unroll
        for (int ni = 0; ni < 4; ni++) {
            int r = r0 + lr;
            int c = n0 + wn * 32 + ni * 8 + 2 * tg;
            float2 v01 = make_float2(acc[mi][ni][0] * w0, acc[mi][ni][1] * w0);
            float2 v23 = make_float2(acc[mi][ni][2] * w1r, acc[mi][ni][3] * w1r);
            *(float2*)(g_y + (size_t)r * HIDDEN + c) = v01;
            *(float2*)(g_y + (size_t)(r + 8) * HIDDEN + c) = v23;
        }
    }
}

// ---------------- combine: out[b] = y[row(b,0)] + y[row(b,1)] ----------------
__global__ void combine_kernel(float* __restrict__ out) {
    int b = blockIdx.x;
    int t = threadIdx.x;
    int r0 = g_rowof[2 * b];
    int r1 = g_rowof[2 * b + 1];
    float4 v0 = *(const float4*)(g_y + (size_t)r0 * HIDDEN + t * 4);
    float4 v1 = *(const float4*)(g_y + (size_t)r1 * HIDDEN + t * 4);
    float4 o;
    o.x = v0.x + v1.x; o.y = v0.y + v1.y; o.z = v0.z + v1.z; o.w = v0.w + v1.w;
    *(float4*)(out + (size_t)b * HIDDEN + t * 4) = o;
}

// ---------------- launch ----------------
extern "C" void kernel_launch(void* const* d_in, const int* in_sizes, int n_in,
                              void* d_out, int out_size) {
    // Identify inputs by element count (robust to metadata ordering):
    //   hidden_states: 2048*1024 = 2,097,152 (unique)
    //   w1 / w2:       8*1024*4096 = 33,554,432 (ambiguous pair -> device probe)
    //   routing_weights / expert_indices: 4096 (ambiguous pair -> device probe)
    const float* x = nullptr;
    const float* big[2] = {nullptr, nullptr};
    const void*  sm[2]  = {nullptr, nullptr};
    int nb = 0, ns = 0;
    for (int i = 0; i < n_in; i++) {
        long long sz = in_sizes[i];
        if (sz == (long long)BATCH * HIDDEN) {
            x = (const float*)d_in[i];
        } else if (sz == (long long)NUM_EXPERTS * HIDDEN * FFN) {
            if (nb < 2) big[nb++] = (const float*)d_in[i];
        } else if (sz == (long long)PAIRS) {
            if (ns < 2) sm[ns++] = d_in[i];
        }
    }
    float* out = (float*)d_out;

    // Defensive: if classification failed, skip launches (output stays poisoned,
    // failure mode is then diagnosable as wrong-output rather than a crash).
    if (!x || nb != 2 || ns != 2) return;

    route_kernel<<<1, 256>>>(sm[0], sm[1], big[0], big[1]);
    gemm1_kernel<<<dim3(MAX_MT, FFN / BN), 256>>>(x, big[0], big[1]);
    gemm2_kernel<<<dim3(MAX_MT, HIDDEN / BN), 256>>>(big[0], big[1]);
    combine_kernel<<<BATCH, 256>>>(out);
}

// round 6
// speedup vs baseline: 1.9598x; 1.9598x over previous
#include <cuda_runtime.h>
#include <cstdint>

#define NUM_EXPERTS 8
#define TOPK 2
#define BATCH 2048
#define HIDDEN 1024
#define FFN 4096
#define PAIRS (BATCH * TOPK)          // 4096
#define BM 128
#define BN 128
#define BKT 16
#define BSTRIDE 132                   // Bs row stride (floats): 132 mod 32 = 4 -> conflict-free
#define ROWS_CAP (PAIRS + NUM_EXPERTS * BM)   // 5120
#define MAX_MT (PAIRS / BM + NUM_EXPERTS)     // 40

// ---------------- scratch (static device globals; no allocation) ----------------
__device__ float g_h1[(size_t)ROWS_CAP * FFN];     // 80 MB intermediate silu(x@w1)
__device__ float g_y[(size_t)ROWS_CAP * HIDDEN];   // 20 MB per-pair outputs (rw applied)
__device__ int   g_row_token[ROWS_CAP];
__device__ float g_row_rw[ROWS_CAP];
__device__ int   g_rowof[PAIRS];
__device__ int   g_tile_e[MAX_MT];
__device__ int   g_tile_r0[MAX_MT];
__device__ int   g_ntiles;
__device__ int   g_sel_w1;   // 1 -> big0 is w1, else big1 is w1

// ---------------- helpers ----------------
__device__ __forceinline__ float to_tf32(float x) {
    asm("cvt.rna.tf32.f32 %0, %1;" : "=f"(x) : "f"(x));
    return x;
}

__device__ __forceinline__ void mma_tf32(float c[4],
                                         uint32_t a0, uint32_t a1, uint32_t a2, uint32_t a3,
                                         uint32_t b0, uint32_t b1) {
    asm volatile(
        "mma.sync.aligned.m16n8k8.row.col.f32.tf32.tf32.f32 "
        "{%0,%1,%2,%3},{%4,%5,%6,%7},{%8,%9},{%0,%1,%2,%3};\n"
        : "+f"(c[0]), "+f"(c[1]), "+f"(c[2]), "+f"(c[3])
        : "r"(a0), "r"(a1), "r"(a2), "r"(a3), "r"(b0), "r"(b1));
}

__device__ __forceinline__ float silu(float v) {
    return v * (1.0f / (1.0f + __expf(-v)));
}

// cp.async 16B with zero-fill when invalid (src-size = 0)
__device__ __forceinline__ void cp16(void* dst, const void* src, bool valid) {
    uint32_t d = (uint32_t)__cvta_generic_to_shared(dst);
    int sz = valid ? 16 : 0;
    asm volatile("cp.async.cg.shared.global [%0], [%1], 16, %2;\n"
                 :: "r"(d), "l"(src), "r"(sz));
}
__device__ __forceinline__ void cp_commit() {
    asm volatile("cp.async.commit_group;\n");
}
__device__ __forceinline__ void cp_wait1() {
    asm volatile("cp.async.wait_group 1;\n");
}

// ---------------- routing: probe inputs + counting sort by expert ----------------
__global__ void route_kernel(const void* __restrict__ sm0,
                             const void* __restrict__ sm1,
                             const float* __restrict__ big0,
                             const float* __restrict__ big1) {
    __shared__ int cnt[NUM_EXPERTS];
    __shared__ int off[NUM_EXPERTS];
    __shared__ int cur[NUM_EXPERTS];
    __shared__ int s_sel_idx;
    __shared__ int s_idx64;
    __shared__ float s_ss0, s_ss1;
    int t = threadIdx.x;

    if (t == 0) {
        int sel = 0, w64 = 1;
        {   const long long* q = (const long long*)sm0;
            bool ok = true;
            for (int i = 0; i < 32; i++) { long long v = q[i]; if (v < 0 || v >= NUM_EXPERTS) ok = false; }
            if (ok) { sel = 1; w64 = 1; goto done; } }
        {   const int* q = (const int*)sm0;
            bool ok = true;
            for (int i = 0; i < 32; i++) { int v = q[i]; if (v < 0 || v >= NUM_EXPERTS) ok = false; }
            if (ok) { sel = 1; w64 = 0; goto done; } }
        {   const long long* q = (const long long*)sm1;
            bool ok = true;
            for (int i = 0; i < 32; i++) { long long v = q[i]; if (v < 0 || v >= NUM_EXPERTS) ok = false; }
            if (ok) { sel = 0; w64 = 1; goto done; } }
        sel = 0; w64 = 0;
    done:
        s_sel_idx = sel; s_idx64 = w64;
        s_ss0 = 0.f; s_ss1 = 0.f;
    }
    if (t < NUM_EXPERTS) cnt[t] = 0;
    __syncthreads();

    {   // w1 (var 1/1024) vs w2 (var 1/4096), 32768 samples -> >30 sigma
        float a0 = 0.f, a1 = 0.f;
        for (int i = t; i < 32768; i += blockDim.x) {
            float v0 = big0[i]; a0 += v0 * v0;
            float v1 = big1[i]; a1 += v1 * v1;
        }
        atomicAdd(&s_ss0, a0);
        atomicAdd(&s_ss1, a1);
    }
    __syncthreads();
    if (t == 0) g_sel_w1 = (s_ss0 > s_ss1) ? 1 : 0;

    const void*  idxp = s_sel_idx ? sm0 : sm1;
    const float* rw   = s_sel_idx ? (const float*)sm1 : (const float*)sm0;
    int idx64 = s_idx64;

    for (int p = t; p < PAIRS; p += blockDim.x) {
        int e = idx64 ? (int)((const long long*)idxp)[p] : ((const int*)idxp)[p];
        atomicAdd(&cnt[e], 1);
    }
    for (int r = t; r < ROWS_CAP; r += blockDim.x)
        g_row_token[r] = -1;
    __syncthreads();
    if (t == 0) {
        int o = 0, nt = 0;
        for (int e = 0; e < NUM_EXPERTS; e++) {
            off[e] = o; cur[e] = 0;
            int ntile = (cnt[e] + BM - 1) / BM;
            for (int i = 0; i < ntile; i++) {
                g_tile_e[nt] = e;
                g_tile_r0[nt] = o + i * BM;
                nt++;
            }
            o += ntile * BM;
        }
        g_ntiles = nt;
    }
    __syncthreads();
    for (int p = t; p < PAIRS; p += blockDim.x) {
        int e = idx64 ? (int)((const long long*)idxp)[p] : ((const int*)idxp)[p];
        int r = off[e] + atomicAdd(&cur[e], 1);
        g_row_token[r] = p >> 1;
        g_row_rw[r] = rw[p];
        g_rowof[p] = r;
    }
}

// ---------------- GEMM1: h1 = silu( gather(X) @ w1[e] ) -- cp.async 2-stage pipeline ----
__global__ __launch_bounds__(256, 2) void gemm1_kernel(const float* __restrict__ x,
                                                       const float* __restrict__ big0,
                                                       const float* __restrict__ big1) {
    int mt = blockIdx.x;
    if (mt >= g_ntiles) return;
    const float* w1 = g_sel_w1 ? big0 : big1;
    int e  = g_tile_e[mt];
    int r0 = g_tile_r0[mt];
    int n0 = blockIdx.y * BN;

    __shared__ __align__(16) float As[2][BM][20];       // [stage][row][k], raw fp32
    __shared__ __align__(16) float Bs[2][BKT][BSTRIDE]; // [stage][k][n], raw fp32
    __shared__ int stok[BM];

    int t = threadIdx.x;
    for (int i = t; i < BM; i += 256) stok[i] = g_row_token[r0 + i];
    __syncthreads();

    int lane = t & 31, warp = t >> 5;
    int wm = warp >> 2, wn = warp & 3;   // 2 x 4 warps; warp tile 64x32
    int g = lane >> 2, tg = lane & 3;

    // per-thread copy coordinates (2 chunks A, 2 chunks B per stage)
    int a_row0 = t >> 2,            a_kv0 = (t & 3) * 4;
    int a_row1 = (t + 256) >> 2,    a_kv1 = ((t + 256) & 3) * 4;
    int b_k0i  = t >> 5,            b_nv0 = (t & 31) * 4;
    int b_k1i  = (t + 256) >> 5,    b_nv1 = ((t + 256) & 31) * 4;
    int tokA0 = stok[a_row0], tokA1 = stok[a_row1];
    const float* aSrc0 = x + (size_t)(tokA0 < 0 ? 0 : tokA0) * HIDDEN + a_kv0;
    const float* aSrc1 = x + (size_t)(tokA1 < 0 ? 0 : tokA1) * HIDDEN + a_kv1;
    const float* wB = w1 + (size_t)e * HIDDEN * FFN + n0;

    float acc[4][4][4];
#pragma unroll
    for (int mi = 0; mi < 4; mi++)
#pragma unroll
        for (int ni = 0; ni < 4; ni++)
#pragma unroll
            for (int c = 0; c < 4; c++) acc[mi][ni][c] = 0.0f;

    // prologue: stage 0 <- k0 = 0
    cp16(&As[0][a_row0][a_kv0], aSrc0, tokA0 >= 0);
    cp16(&As[0][a_row1][a_kv1], aSrc1, tokA1 >= 0);
    cp16(&Bs[0][b_k0i][b_nv0], wB + (size_t)b_k0i * FFN + b_nv0, true);
    cp16(&Bs[0][b_k1i][b_nv1], wB + (size_t)b_k1i * FFN + b_nv1, true);
    cp_commit();

    for (int k0 = 0; k0 < HIDDEN; k0 += BKT) {
        int s  = (k0 / BKT) & 1;
        int k1 = k0 + BKT;
        if (k1 < HIDDEN) {
            int sn = s ^ 1;
            cp16(&As[sn][a_row0][a_kv0], aSrc0 + k1, tokA0 >= 0);
            cp16(&As[sn][a_row1][a_kv1], aSrc1 + k1, tokA1 >= 0);
            cp16(&Bs[sn][b_k0i][b_nv0], wB + (size_t)(k1 + b_k0i) * FFN + b_nv0, true);
            cp16(&Bs[sn][b_k1i][b_nv1], wB + (size_t)(k1 + b_k1i) * FFN + b_nv1, true);
        }
        cp_commit();
        cp_wait1();
        __syncthreads();

#pragma unroll
        for (int kk = 0; kk < BKT; kk += 8) {
            uint32_t a[4][4], b[4][2];
#pragma unroll
            for (int mi = 0; mi < 4; mi++) {
                int r = wm * 64 + mi * 16;
                a[mi][0] = __float_as_uint(to_tf32(As[s][r + g][kk + tg]));
                a[mi][1] = __float_as_uint(to_tf32(As[s][r + g + 8][kk + tg]));
                a[mi][2] = __float_as_uint(to_tf32(As[s][r + g][kk + tg + 4]));
                a[mi][3] = __float_as_uint(to_tf32(As[s][r + g + 8][kk + tg + 4]));
            }
#pragma unroll
            for (int ni = 0; ni < 4; ni++) {
                int n = wn * 32 + ni * 8;
                b[ni][0] = __float_as_uint(to_tf32(Bs[s][kk + tg][n + g]));
                b[ni][1] = __float_as_uint(to_tf32(Bs[s][kk + tg + 4][n + g]));
            }
#pragma unroll
            for (int mi = 0; mi < 4; mi++)
#pragma unroll
                for (int ni = 0; ni < 4; ni++)
                    mma_tf32(acc[mi][ni], a[mi][0], a[mi][1], a[mi][2], a[mi][3],
                             b[ni][0], b[ni][1]);
        }
        __syncthreads();
    }

#pragma unroll
    for (int mi = 0; mi < 4; mi++) {
#pragma unroll
        for (int ni = 0; ni < 4; ni++) {
            int r = r0 + wm * 64 + mi * 16 + g;
            int c = n0 + wn * 32 + ni * 8 + 2 * tg;
            float2 v01 = make_float2(silu(acc[mi][ni][0]), silu(acc[mi][ni][1]));
            float2 v23 = make_float2(silu(acc[mi][ni][2]), silu(acc[mi][ni][3]));
            *(float2*)(g_h1 + (size_t)r * FFN + c) = v01;
            *(float2*)(g_h1 + (size_t)(r + 8) * FFN + c) = v23;
        }
    }
}

// ---------------- GEMM2: y = (h1 @ w2[e]) * rw -- cp.async 2-stage pipeline ----------
__global__ __launch_bounds__(256, 2) void gemm2_kernel(const float* __restrict__ big0,
                                                       const float* __restrict__ big1) {
    int mt = blockIdx.x;
    if (mt >= g_ntiles) return;
    const float* w2 = g_sel_w1 ? big1 : big0;
    int e  = g_tile_e[mt];
    int r0 = g_tile_r0[mt];
    int n0 = blockIdx.y * BN;

    __shared__ __align__(16) float As[2][BM][20];
    __shared__ __align__(16) float Bs[2][BKT][BSTRIDE];
    __shared__ float srw[BM];

    int t = threadIdx.x;
    for (int i = t; i < BM; i += 256) srw[i] = g_row_rw[r0 + i];
    __syncthreads();

    int lane = t & 31, warp = t >> 5;
    int wm = warp >> 2, wn = warp & 3;
    int g = lane >> 2, tg = lane & 3;

    int a_row0 = t >> 2,            a_kv0 = (t & 3) * 4;
    int a_row1 = (t + 256) >> 2,    a_kv1 = ((t + 256) & 3) * 4;
    int b_k0i  = t >> 5,            b_nv0 = (t & 31) * 4;
    int b_k1i  = (t + 256) >> 5,    b_nv1 = ((t + 256) & 31) * 4;
    const float* aSrc0 = g_h1 + (size_t)(r0 + a_row0) * FFN + a_kv0;
    const float* aSrc1 = g_h1 + (size_t)(r0 + a_row1) * FFN + a_kv1;
    const float* wB = w2 + (size_t)e * FFN * HIDDEN + n0;

    float acc[4][4][4];
#pragma unroll
    for (int mi = 0; mi < 4; mi++)
#pragma unroll
        for (int ni = 0; ni < 4; ni++)
#pragma unroll
            for (int c = 0; c < 4; c++) acc[mi][ni][c] = 0.0f;

    cp16(&As[0][a_row0][a_kv0], aSrc0, true);
    cp16(&As[0][a_row1][a_kv1], aSrc1, true);
    cp16(&Bs[0][b_k0i][b_nv0], wB + (size_t)b_k0i * HIDDEN + b_nv0, true);
    cp16(&Bs[0][b_k1i][b_nv1], wB + (size_t)b_k1i * HIDDEN + b_nv1, true);
    cp_commit();

    for (int k0 = 0; k0 < FFN; k0 += BKT) {
        int s  = (k0 / BKT) & 1;
        int k1 = k0 + BKT;
        if (k1 < FFN) {
            int sn = s ^ 1;
            cp16(&As[sn][a_row0][a_kv0], aSrc0 + k1, true);
            cp16(&As[sn][a_row1][a_kv1], aSrc1 + k1, true);
            cp16(&Bs[sn][b_k0i][b_nv0], wB + (size_t)(k1 + b_k0i) * HIDDEN + b_nv0, true);
            cp16(&Bs[sn][b_k1i][b_nv1], wB + (size_t)(k1 + b_k1i) * HIDDEN + b_nv1, true);
        }
        cp_commit();
        cp_wait1();
        __syncthreads();

#pragma unroll
        for (int kk = 0; kk < BKT; kk += 8) {
            uint32_t a[4][4], b[4][2];
#pragma unroll
            for (int mi = 0; mi < 4; mi++) {
                int r = wm * 64 + mi * 16;
                a[mi][0] = __float_as_uint(to_tf32(As[s][r + g][kk + tg]));
                a[mi][1] = __float_as_uint(to_tf32(As[s][r + g + 8][kk + tg]));
                a[mi][2] = __float_as_uint(to_tf32(As[s][r + g][kk + tg + 4]));
                a[mi][3] = __float_as_uint(to_tf32(As[s][r + g + 8][kk + tg + 4]));
            }
#pragma unroll
            for (int ni = 0; ni < 4; ni++) {
                int n = wn * 32 + ni * 8;
                b[ni][0] = __float_as_uint(to_tf32(Bs[s][kk + tg][n + g]));
                b[ni][1] = __float_as_uint(to_tf32(Bs[s][kk + tg + 4][n + g]));
            }
#pragma unroll
            for (int mi = 0; mi < 4; mi++)
#pragma unroll
                for (int ni = 0; ni < 4; ni++)
                    mma_tf32(acc[mi][ni], a[mi][0], a[mi][1], a[mi][2], a[mi][3],
                             b[ni][0], b[ni][1]);
        }
        __syncthreads();
    }

#pragma unroll
    for (int mi = 0; mi < 4; mi++) {
        int lr = wm * 64 + mi * 16 + g;
        float w0 = srw[lr];
        float w1r = srw[lr + 8];
#pragma unroll
        for (int ni = 0; ni < 4; ni++) {
            int r = r0 + lr;
            int c = n0 + wn * 32 + ni * 8 + 2 * tg;
            float2 v01 = make_float2(acc[mi][ni][0] * w0, acc[mi][ni][1] * w0);
            float2 v23 = make_float2(acc[mi][ni][2] * w1r, acc[mi][ni][3] * w1r);
            *(float2*)(g_y + (size_t)r * HIDDEN + c) = v01;
            *(float2*)(g_y + (size_t)(r + 8) * HIDDEN + c) = v23;
        }
    }
}

// ---------------- combine: out[b] = y[row(b,0)] + y[row(b,1)] ----------------
__global__ void combine_kernel(float* __restrict__ out) {
    int b = blockIdx.x;
    int t = threadIdx.x;
    int r0 = g_rowof[2 * b];
    int r1 = g_rowof[2 * b + 1];
    float4 v0 = *(const float4*)(g_y + (size_t)r0 * HIDDEN + t * 4);
    float4 v1 = *(const float4*)(g_y + (size_t)r1 * HIDDEN + t * 4);
    float4 o;
    o.x = v0.x + v1.x; o.y = v0.y + v1.y; o.z = v0.z + v1.z; o.w = v0.w + v1.w;
    *(float4*)(out + (size_t)b * HIDDEN + t * 4) = o;
}

// ---------------- launch ----------------
extern "C" void kernel_launch(void* const* d_in, const int* in_sizes, int n_in,
                              void* d_out, int out_size) {
    const float* x = nullptr;
    const float* big[2] = {nullptr, nullptr};
    const void*  sm[2]  = {nullptr, nullptr};
    int nb = 0, ns = 0;
    for (int i = 0; i < n_in; i++) {
        long long sz = in_sizes[i];
        if (sz == (long long)BATCH * HIDDEN) {
            x = (const float*)d_in[i];
        } else if (sz == (long long)NUM_EXPERTS * HIDDEN * FFN) {
            if (nb < 2) big[nb++] = (const float*)d_in[i];
        } else if (sz == (long long)PAIRS) {
            if (ns < 2) sm[ns++] = d_in[i];
        }
    }
    float* out = (float*)d_out;
    if (!x || nb != 2 || ns != 2) return;

    route_kernel<<<1, 256>>>(sm[0], sm[1], big[0], big[1]);
    gemm1_kernel<<<dim3(MAX_MT, FFN / BN), 256>>>(x, big[0], big[1]);
    gemm2_kernel<<<dim3(MAX_MT, HIDDEN / BN), 256>>>(big[0], big[1]);
    combine_kernel<<<BATCH, 256>>>(out);
}

// round 7
// speedup vs baseline: 2.0461x; 1.0440x over previous
#include <cuda_runtime.h>
#include <cstdint>

#define NUM_EXPERTS 8
#define TOPK 2
#define BATCH 2048
#define HIDDEN 1024
#define FFN 4096
#define PAIRS (BATCH * TOPK)          // 4096
#define BM 128
#define BN 256
#define BKT 16
#define BSTRIDE 264                   // Bs row stride (floats); (row*264+col)%32 pattern conflict-free
#define ROWS_CAP (PAIRS + NUM_EXPERTS * BM)   // 5120
#define MAX_MT (PAIRS / BM + NUM_EXPERTS)     // 40

// ---------------- scratch (static device globals; no allocation) ----------------
__device__ float g_h1[(size_t)ROWS_CAP * FFN];     // 80 MB intermediate silu(x@w1)
__device__ float g_y[(size_t)ROWS_CAP * HIDDEN];   // 20 MB per-pair outputs (rw applied)
__device__ int   g_row_token[ROWS_CAP];
__device__ float g_row_rw[ROWS_CAP];
__device__ int   g_rowof[PAIRS];
__device__ int   g_tile_e[MAX_MT];
__device__ int   g_tile_r0[MAX_MT];
__device__ int   g_ntiles;
__device__ int   g_sel_w1;   // 1 -> big0 is w1, else big1 is w1

// dynamic smem layouts
struct SmemG1 {
    float As[2][BM][20];        // [stage][row][k]
    float Bs[2][BKT][BSTRIDE];  // [stage][k][n]
    int   stok[BM];
};
struct SmemG2 {
    float As[2][BM][20];
    float Bs[2][BKT][BSTRIDE];
    float srw[BM];
};

// ---------------- helpers ----------------
__device__ __forceinline__ float to_tf32(float x) {
    asm("cvt.rna.tf32.f32 %0, %1;" : "=f"(x) : "f"(x));
    return x;
}

__device__ __forceinline__ void mma_tf32(float c[4],
                                         uint32_t a0, uint32_t a1, uint32_t a2, uint32_t a3,
                                         uint32_t b0, uint32_t b1) {
    asm volatile(
        "mma.sync.aligned.m16n8k8.row.col.f32.tf32.tf32.f32 "
        "{%0,%1,%2,%3},{%4,%5,%6,%7},{%8,%9},{%0,%1,%2,%3};\n"
        : "+f"(c[0]), "+f"(c[1]), "+f"(c[2]), "+f"(c[3])
        : "r"(a0), "r"(a1), "r"(a2), "r"(a3), "r"(b0), "r"(b1));
}

__device__ __forceinline__ float silu(float v) {
    return v * (1.0f / (1.0f + __expf(-v)));
}

// cp.async 16B with zero-fill when invalid (src-size = 0)
__device__ __forceinline__ void cp16(void* dst, const void* src, bool valid) {
    uint32_t d = (uint32_t)__cvta_generic_to_shared(dst);
    int sz = valid ? 16 : 0;
    asm volatile("cp.async.cg.shared.global [%0], [%1], 16, %2;\n"
                 :: "r"(d), "l"(src), "r"(sz));
}
__device__ __forceinline__ void cp_commit() {
    asm volatile("cp.async.commit_group;\n");
}
__device__ __forceinline__ void cp_wait1() {
    asm volatile("cp.async.wait_group 1;\n");
}

// ---------------- routing: probe inputs + counting sort by expert ----------------
__global__ void route_kernel(const void* __restrict__ sm0,
                             const void* __restrict__ sm1,
                             const float* __restrict__ big0,
                             const float* __restrict__ big1) {
    __shared__ int cnt[NUM_EXPERTS];
    __shared__ int off[NUM_EXPERTS];
    __shared__ int cur[NUM_EXPERTS];
    __shared__ int s_sel_idx;
    __shared__ int s_idx64;
    __shared__ float s_ss0, s_ss1;
    int t = threadIdx.x;

    if (t == 0) {
        int sel = 0, w64 = 1;
        {   const long long* q = (const long long*)sm0;
            bool ok = true;
            for (int i = 0; i < 32; i++) { long long v = q[i]; if (v < 0 || v >= NUM_EXPERTS) ok = false; }
            if (ok) { sel = 1; w64 = 1; goto done; } }
        {   const int* q = (const int*)sm0;
            bool ok = true;
            for (int i = 0; i < 32; i++) { int v = q[i]; if (v < 0 || v >= NUM_EXPERTS) ok = false; }
            if (ok) { sel = 1; w64 = 0; goto done; } }
        {   const long long* q = (const long long*)sm1;
            bool ok = true;
            for (int i = 0; i < 32; i++) { long long v = q[i]; if (v < 0 || v >= NUM_EXPERTS) ok = false; }
            if (ok) { sel = 0; w64 = 1; goto done; } }
        sel = 0; w64 = 0;
    done:
        s_sel_idx = sel; s_idx64 = w64;
        s_ss0 = 0.f; s_ss1 = 0.f;
    }
    if (t < NUM_EXPERTS) cnt[t] = 0;
    __syncthreads();

    {   // w1 (var 1/1024) vs w2 (var 1/4096), 32768 samples -> >30 sigma
        float a0 = 0.f, a1 = 0.f;
        for (int i = t; i < 32768; i += blockDim.x) {
            float v0 = big0[i]; a0 += v0 * v0;
            float v1 = big1[i]; a1 += v1 * v1;
        }
        atomicAdd(&s_ss0, a0);
        atomicAdd(&s_ss1, a1);
    }
    __syncthreads();
    if (t == 0) g_sel_w1 = (s_ss0 > s_ss1) ? 1 : 0;

    const void*  idxp = s_sel_idx ? sm0 : sm1;
    const float* rw   = s_sel_idx ? (const float*)sm1 : (const float*)sm0;
    int idx64 = s_idx64;

    for (int p = t; p < PAIRS; p += blockDim.x) {
        int e = idx64 ? (int)((const long long*)idxp)[p] : ((const int*)idxp)[p];
        atomicAdd(&cnt[e], 1);
    }
    for (int r = t; r < ROWS_CAP; r += blockDim.x)
        g_row_token[r] = -1;
    __syncthreads();
    if (t == 0) {
        int o = 0, nt = 0;
        for (int e = 0; e < NUM_EXPERTS; e++) {
            off[e] = o; cur[e] = 0;
            int ntile = (cnt[e] + BM - 1) / BM;
            for (int i = 0; i < ntile; i++) {
                g_tile_e[nt] = e;
                g_tile_r0[nt] = o + i * BM;
                nt++;
            }
            o += ntile * BM;
        }
        g_ntiles = nt;
    }
    __syncthreads();
    for (int p = t; p < PAIRS; p += blockDim.x) {
        int e = idx64 ? (int)((const long long*)idxp)[p] : ((const int*)idxp)[p];
        int r = off[e] + atomicAdd(&cur[e], 1);
        g_row_token[r] = p >> 1;
        g_row_rw[r] = rw[p];
        g_rowof[p] = r;
    }
}

// ---------------- GEMM1: h1 = silu( gather(X) @ w1[e] ), 128x256 tile, warp 64x64 ----
__global__ __launch_bounds__(256, 1) void gemm1_kernel(const float* __restrict__ x,
                                                       const float* __restrict__ big0,
                                                       const float* __restrict__ big1) {
    int mt = blockIdx.x;
    if (mt >= g_ntiles) return;
    const float* w1 = g_sel_w1 ? big0 : big1;
    int e  = g_tile_e[mt];
    int r0 = g_tile_r0[mt];
    int n0 = blockIdx.y * BN;

    extern __shared__ __align__(16) char smem_raw[];
    SmemG1& S = *reinterpret_cast<SmemG1*>(smem_raw);

    int t = threadIdx.x;
    for (int i = t; i < BM; i += 256) S.stok[i] = g_row_token[r0 + i];
    __syncthreads();

    int lane = t & 31, warp = t >> 5;
    int wm = warp >> 2, wn = warp & 3;   // 2 x 4 warps; warp tile 64x64
    int g = lane >> 2, tg = lane & 3;

    // copy coords: A 2 chunks/thread (512 total), B 4 chunks/thread (1024 total)
    int a_row0 = t >> 2,            a_kv0 = (t & 3) * 4;
    int a_row1 = (t + 256) >> 2,    a_kv1 = ((t + 256) & 3) * 4;
    int tokA0 = S.stok[a_row0], tokA1 = S.stok[a_row1];
    const float* aSrc0 = x + (size_t)(tokA0 < 0 ? 0 : tokA0) * HIDDEN + a_kv0;
    const float* aSrc1 = x + (size_t)(tokA1 < 0 ? 0 : tokA1) * HIDDEN + a_kv1;
    const float* wB = w1 + (size_t)e * HIDDEN * FFN + n0;
    int b_k[4], b_nv[4];
#pragma unroll
    for (int j = 0; j < 4; j++) {
        int q = t + j * 256;
        b_k[j]  = q >> 6;            // 64 chunks per k-row (256 floats)
        b_nv[j] = (q & 63) * 4;
    }

    float acc[4][8][4];
#pragma unroll
    for (int mi = 0; mi < 4; mi++)
#pragma unroll
        for (int ni = 0; ni < 8; ni++)
#pragma unroll
            for (int c = 0; c < 4; c++) acc[mi][ni][c] = 0.0f;

    // prologue: stage 0 <- k0 = 0
    cp16(&S.As[0][a_row0][a_kv0], aSrc0, tokA0 >= 0);
    cp16(&S.As[0][a_row1][a_kv1], aSrc1, tokA1 >= 0);
#pragma unroll
    for (int j = 0; j < 4; j++)
        cp16(&S.Bs[0][b_k[j]][b_nv[j]], wB + (size_t)b_k[j] * FFN + b_nv[j], true);
    cp_commit();

    for (int k0 = 0; k0 < HIDDEN; k0 += BKT) {
        int s  = (k0 / BKT) & 1;
        int k1 = k0 + BKT;
        if (k1 < HIDDEN) {
            int sn = s ^ 1;
            cp16(&S.As[sn][a_row0][a_kv0], aSrc0 + k1, tokA0 >= 0);
            cp16(&S.As[sn][a_row1][a_kv1], aSrc1 + k1, tokA1 >= 0);
#pragma unroll
            for (int j = 0; j < 4; j++)
                cp16(&S.Bs[sn][b_k[j]][b_nv[j]], wB + (size_t)(k1 + b_k[j]) * FFN + b_nv[j], true);
        }
        cp_commit();
        cp_wait1();
        __syncthreads();

#pragma unroll
        for (int kk = 0; kk < BKT; kk += 8) {
            uint32_t a[4][4], b[8][2];
#pragma unroll
            for (int mi = 0; mi < 4; mi++) {
                int r = wm * 64 + mi * 16;
                a[mi][0] = __float_as_uint(to_tf32(S.As[s][r + g][kk + tg]));
                a[mi][1] = __float_as_uint(to_tf32(S.As[s][r + g + 8][kk + tg]));
                a[mi][2] = __float_as_uint(to_tf32(S.As[s][r + g][kk + tg + 4]));
                a[mi][3] = __float_as_uint(to_tf32(S.As[s][r + g + 8][kk + tg + 4]));
            }
#pragma unroll
            for (int ni = 0; ni < 8; ni++) {
                int n = wn * 64 + ni * 8;
                b[ni][0] = __float_as_uint(to_tf32(S.Bs[s][kk + tg][n + g]));
                b[ni][1] = __float_as_uint(to_tf32(S.Bs[s][kk + tg + 4][n + g]));
            }
#pragma unroll
            for (int mi = 0; mi < 4; mi++)
#pragma unroll
                for (int ni = 0; ni < 8; ni++)
                    mma_tf32(acc[mi][ni], a[mi][0], a[mi][1], a[mi][2], a[mi][3],
                             b[ni][0], b[ni][1]);
        }
        __syncthreads();
    }

#pragma unroll
    for (int mi = 0; mi < 4; mi++) {
#pragma unroll
        for (int ni = 0; ni < 8; ni++) {
            int r = r0 + wm * 64 + mi * 16 + g;
            int c = n0 + wn * 64 + ni * 8 + 2 * tg;
            float2 v01 = make_float2(silu(acc[mi][ni][0]), silu(acc[mi][ni][1]));
            float2 v23 = make_float2(silu(acc[mi][ni][2]), silu(acc[mi][ni][3]));
            *(float2*)(g_h1 + (size_t)r * FFN + c) = v01;
            *(float2*)(g_h1 + (size_t)(r + 8) * FFN + c) = v23;
        }
    }
}

// ---------------- GEMM2: y = (h1 @ w2[e]) * rw, 128x256 tile, warp 64x64 ------------
__global__ __launch_bounds__(256, 1) void gemm2_kernel(const float* __restrict__ big0,
                                                       const float* __restrict__ big1) {
    int mt = blockIdx.x;
    if (mt >= g_ntiles) return;
    const float* w2 = g_sel_w1 ? big1 : big0;
    int e  = g_tile_e[mt];
    int r0 = g_tile_r0[mt];
    int n0 = blockIdx.y * BN;

    extern __shared__ __align__(16) char smem_raw[];
    SmemG2& S = *reinterpret_cast<SmemG2*>(smem_raw);

    int t = threadIdx.x;
    for (int i = t; i < BM; i += 256) S.srw[i] = g_row_rw[r0 + i];
    __syncthreads();

    int lane = t & 31, warp = t >> 5;
    int wm = warp >> 2, wn = warp & 3;
    int g = lane >> 2, tg = lane & 3;

    int a_row0 = t >> 2,            a_kv0 = (t & 3) * 4;
    int a_row1 = (t + 256) >> 2,    a_kv1 = ((t + 256) & 3) * 4;
    const float* aSrc0 = g_h1 + (size_t)(r0 + a_row0) * FFN + a_kv0;
    const float* aSrc1 = g_h1 + (size_t)(r0 + a_row1) * FFN + a_kv1;
    const float* wB = w2 + (size_t)e * FFN * HIDDEN + n0;
    int b_k[4], b_nv[4];
#pragma unroll
    for (int j = 0; j < 4; j++) {
        int q = t + j * 256;
        b_k[j]  = q >> 6;
        b_nv[j] = (q & 63) * 4;
    }

    float acc[4][8][4];
#pragma unroll
    for (int mi = 0; mi < 4; mi++)
#pragma unroll
        for (int ni = 0; ni < 8; ni++)
#pragma unroll
            for (int c = 0; c < 4; c++) acc[mi][ni][c] = 0.0f;

    cp16(&S.As[0][a_row0][a_kv0], aSrc0, true);
    cp16(&S.As[0][a_row1][a_kv1], aSrc1, true);
#pragma unroll
    for (int j = 0; j < 4; j++)
        cp16(&S.Bs[0][b_k[j]][b_nv[j]], wB + (size_t)b_k[j] * HIDDEN + b_nv[j], true);
    cp_commit();

    for (int k0 = 0; k0 < FFN; k0 += BKT) {
        int s  = (k0 / BKT) & 1;
        int k1 = k0 + BKT;
        if (k1 < FFN) {
            int sn = s ^ 1;
            cp16(&S.As[sn][a_row0][a_kv0], aSrc0 + k1, true);
            cp16(&S.As[sn][a_row1][a_kv1], aSrc1 + k1, true);
#pragma unroll
            for (int j = 0; j < 4; j++)
                cp16(&S.Bs[sn][b_k[j]][b_nv[j]], wB + (size_t)(k1 + b_k[j]) * HIDDEN + b_nv[j], true);
        }
        cp_commit();
        cp_wait1();
        __syncthreads();

#pragma unroll
        for (int kk = 0; kk < BKT; kk += 8) {
            uint32_t a[4][4], b[8][2];
#pragma unroll
            for (int mi = 0; mi < 4; mi++) {
                int r = wm * 64 + mi * 16;
                a[mi][0] = __float_as_uint(to_tf32(S.As[s][r + g][kk + tg]));
                a[mi][1] = __float_as_uint(to_tf32(S.As[s][r + g + 8][kk + tg]));
                a[mi][2] = __float_as_uint(to_tf32(S.As[s][r + g][kk + tg + 4]));
                a[mi][3] = __float_as_uint(to_tf32(S.As[s][r + g + 8][kk + tg + 4]));
            }
#pragma unroll
            for (int ni = 0; ni < 8; ni++) {
                int n = wn * 64 + ni * 8;
                b[ni][0] = __float_as_uint(to_tf32(S.Bs[s][kk + tg][n + g]));
                b[ni][1] = __float_as_uint(to_tf32(S.Bs[s][kk + tg + 4][n + g]));
            }
#pragma unroll
            for (int mi = 0; mi < 4; mi++)
#pragma unroll
                for (int ni = 0; ni < 8; ni++)
                    mma_tf32(acc[mi][ni], a[mi][0], a[mi][1], a[mi][2], a[mi][3],
                             b[ni][0], b[ni][1]);
        }
        __syncthreads();
    }

#pragma unroll
    for (int mi = 0; mi < 4; mi++) {
        int lr = wm * 64 + mi * 16 + g;
        float w0 = S.srw[lr];
        float w1r = S.srw[lr + 8];
#pragma unroll
        for (int ni = 0; ni < 8; ni++) {
            int r = r0 + lr;
            int c = n0 + wn * 64 + ni * 8 + 2 * tg;
            float2 v01 = make_float2(acc[mi][ni][0] * w0, acc[mi][ni][1] * w0);
            float2 v23 = make_float2(acc[mi][ni][2] * w1r, acc[mi][ni][3] * w1r);
            *(float2*)(g_y + (size_t)r * HIDDEN + c) = v01;
            *(float2*)(g_y + (size_t)(r + 8) * HIDDEN + c) = v23;
        }
    }
}

// ---------------- combine: out[b] = y[row(b,0)] + y[row(b,1)] ----------------
__global__ void combine_kernel(float* __restrict__ out) {
    int b = blockIdx.x;
    int t = threadIdx.x;
    int r0 = g_rowof[2 * b];
    int r1 = g_rowof[2 * b + 1];
    float4 v0 = *(const float4*)(g_y + (size_t)r0 * HIDDEN + t * 4);
    float4 v1 = *(const float4*)(g_y + (size_t)r1 * HIDDEN + t * 4);
    float4 o;
    o.x = v0.x + v1.x; o.y = v0.y + v1.y; o.z = v0.z + v1.z; o.w = v0.w + v1.w;
    *(float4*)(out + (size_t)b * HIDDEN + t * 4) = o;
}

// ---------------- launch ----------------
extern "C" void kernel_launch(void* const* d_in, const int* in_sizes, int n_in,
                              void* d_out, int out_size) {
    const float* x = nullptr;
    const float* big[2] = {nullptr, nullptr};
    const void*  sm[2]  = {nullptr, nullptr};
    int nb = 0, ns = 0;
    for (int i = 0; i < n_in; i++) {
        long long sz = in_sizes[i];
        if (sz == (long long)BATCH * HIDDEN) {
            x = (const float*)d_in[i];
        } else if (sz == (long long)NUM_EXPERTS * HIDDEN * FFN) {
            if (nb < 2) big[nb++] = (const float*)d_in[i];
        } else if (sz == (long long)PAIRS) {
            if (ns < 2) sm[ns++] = d_in[i];
        }
    }
    float* out = (float*)d_out;
    if (!x || nb != 2 || ns != 2) return;

    // dynamic smem (54.8 KB > 48 KB static limit); attribute set is graph-legal
    int smem1 = (int)sizeof(SmemG1);
    int smem2 = (int)sizeof(SmemG2);
    cudaFuncSetAttribute(gemm1_kernel, cudaFuncAttributeMaxDynamicSharedMemorySize, smem1);
    cudaFuncSetAttribute(gemm2_kernel, cudaFuncAttributeMaxDynamicSharedMemorySize, smem2);

    route_kernel<<<1, 256>>>(sm[0], sm[1], big[0], big[1]);
    gemm1_kernel<<<dim3(MAX_MT, FFN / BN), 256, smem1>>>(x, big[0], big[1]);
    gemm2_kernel<<<dim3(MAX_MT, HIDDEN / BN), 256, smem2>>>(big[0], big[1]);
    combine_kernel<<<BATCH, 256>>>(out);
}

// round 9
// speedup vs baseline: 3.0252x; 1.4785x over previous
#include <cuda_runtime.h>
#include <cuda_fp16.h>
#include <cstdint>

#define NUM_EXPERTS 8
#define TOPK 2
#define BATCH 2048
#define HIDDEN 1024
#define FFN 4096
#define PAIRS (BATCH * TOPK)          // 4096
#define BM 128
#define BN 256
#define BK 32                         // k-slab (halves)
#define ROWS_CAP (PAIRS + NUM_EXPERTS * BM)   // 5120
#define MAX_MT (PAIRS / BM + NUM_EXPERTS)     // 40

// smem layout (bytes), dynamic
#define AS_STRIDE 80                  // 32 halves (64B) + 16B pad; 20 words -> conflict-free
#define BS_STRIDE 528                 // 256 halves (512B) + 16B pad; 132 words -> conflict-free
#define SA 0                          // As[2][128][AS_STRIDE]  = 20480 B
#define SA_STAGE (BM * AS_STRIDE)     // 10240
#define SB 20480                      // Bs[2][32][BS_STRIDE]   = 33792 B
#define SB_STAGE (BK * BS_STRIDE)     // 16896
#define SMETA 54272                   // stok/srw, 512 B
#define SMEM_BYTES 54784

// ---------------- scratch (static device globals) ----------------
__device__ __half g_wh0[(size_t)NUM_EXPERTS * HIDDEN * FFN];  // 64 MB: half(big0)
__device__ __half g_wh1[(size_t)NUM_EXPERTS * HIDDEN * FFN];  // 64 MB: half(big1)
__device__ __half g_xh[(size_t)BATCH * HIDDEN];               // 4 MB: half(x)
__device__ __half g_h1h[(size_t)ROWS_CAP * FFN];              // 40 MB: half(silu(x@w1))
__device__ float  g_y[(size_t)ROWS_CAP * HIDDEN];             // 20 MB
__device__ int    g_row_token[ROWS_CAP];
__device__ float  g_row_rw[ROWS_CAP];
__device__ int    g_rowof[PAIRS];
__device__ int    g_tile_e[MAX_MT];
__device__ int    g_tile_r0[MAX_MT];
__device__ int    g_ntiles;
__device__ int    g_sel_w1;   // 1 -> big0/g_wh0 is w1

// ---------------- helpers ----------------
__device__ __forceinline__ float silu(float v) {
    return v * (1.0f / (1.0f + __expf(-v)));
}
__device__ __forceinline__ void cp16s(uint32_t dst, const void* src, bool valid) {
    int sz = valid ? 16 : 0;
    asm volatile("cp.async.cg.shared.global [%0], [%1], 16, %2;\n"
                 :: "r"(dst), "l"(src), "r"(sz));
}
__device__ __forceinline__ void cp_commit() { asm volatile("cp.async.commit_group;\n"); }
__device__ __forceinline__ void cp_wait1()  { asm volatile("cp.async.wait_group 1;\n"); }

__device__ __forceinline__ void ldsm_x4(uint32_t& r0, uint32_t& r1, uint32_t& r2, uint32_t& r3,
                                        uint32_t addr) {
    asm volatile("ldmatrix.sync.aligned.m8n8.x4.shared.b16 {%0,%1,%2,%3}, [%4];"
                 : "=r"(r0), "=r"(r1), "=r"(r2), "=r"(r3) : "r"(addr));
}
__device__ __forceinline__ void ldsm_x4t(uint32_t& r0, uint32_t& r1, uint32_t& r2, uint32_t& r3,
                                         uint32_t addr) {
    asm volatile("ldmatrix.sync.aligned.m8n8.x4.trans.shared.b16 {%0,%1,%2,%3}, [%4];"
                 : "=r"(r0), "=r"(r1), "=r"(r2), "=r"(r3) : "r"(addr));
}
__device__ __forceinline__ void mma_f16(float c[4],
                                        uint32_t a0, uint32_t a1, uint32_t a2, uint32_t a3,
                                        uint32_t b0, uint32_t b1) {
    asm volatile(
        "mma.sync.aligned.m16n8k16.row.col.f32.f16.f16.f32 "
        "{%0,%1,%2,%3},{%4,%5,%6,%7},{%8,%9},{%0,%1,%2,%3};\n"
        : "+f"(c[0]), "+f"(c[1]), "+f"(c[2]), "+f"(c[3])
        : "r"(a0), "r"(a1), "r"(a2), "r"(a3), "r"(b0), "r"(b1));
}

// ---------------- routing: probe inputs + counting sort (unchanged, proven) -----
__global__ void route_kernel(const void* __restrict__ sm0,
                             const void* __restrict__ sm1,
                             const float* __restrict__ big0,
                             const float* __restrict__ big1) {
    __shared__ int cnt[NUM_EXPERTS];
    __shared__ int off[NUM_EXPERTS];
    __shared__ int cur[NUM_EXPERTS];
    __shared__ int s_sel_idx;
    __shared__ int s_idx64;
    __shared__ float s_ss0, s_ss1;
    int t = threadIdx.x;

    if (t == 0) {
        int sel = 0, w64 = 1;
        {   const long long* q = (const long long*)sm0;
            bool ok = true;
            for (int i = 0; i < 32; i++) { long long v = q[i]; if (v < 0 || v >= NUM_EXPERTS) ok = false; }
            if (ok) { sel = 1; w64 = 1; goto done; } }
        {   const int* q = (const int*)sm0;
            bool ok = true;
            for (int i = 0; i < 32; i++) { int v = q[i]; if (v < 0 || v >= NUM_EXPERTS) ok = false; }
            if (ok) { sel = 1; w64 = 0; goto done; } }
        {   const long long* q = (const long long*)sm1;
            bool ok = true;
            for (int i = 0; i < 32; i++) { long long v = q[i]; if (v < 0 || v >= NUM_EXPERTS) ok = false; }
            if (ok) { sel = 0; w64 = 1; goto done; } }
        sel = 0; w64 = 0;
    done:
        s_sel_idx = sel; s_idx64 = w64;
        s_ss0 = 0.f; s_ss1 = 0.f;
    }
    if (t < NUM_EXPERTS) cnt[t] = 0;
    __syncthreads();

    {   float a0 = 0.f, a1 = 0.f;
        for (int i = t; i < 32768; i += blockDim.x) {
            float v0 = big0[i]; a0 += v0 * v0;
            float v1 = big1[i]; a1 += v1 * v1;
        }
        atomicAdd(&s_ss0, a0);
        atomicAdd(&s_ss1, a1);
    }
    __syncthreads();
    if (t == 0) g_sel_w1 = (s_ss0 > s_ss1) ? 1 : 0;

    const void*  idxp = s_sel_idx ? sm0 : sm1;
    const float* rw   = s_sel_idx ? (const float*)sm1 : (const float*)sm0;
    int idx64 = s_idx64;

    for (int p = t; p < PAIRS; p += blockDim.x) {
        int e = idx64 ? (int)((const long long*)idxp)[p] : ((const int*)idxp)[p];
        atomicAdd(&cnt[e], 1);
    }
    for (int r = t; r < ROWS_CAP; r += blockDim.x)
        g_row_token[r] = -1;
    __syncthreads();
    if (t == 0) {
        int o = 0, nt = 0;
        for (int e = 0; e < NUM_EXPERTS; e++) {
            off[e] = o; cur[e] = 0;
            int ntile = (cnt[e] + BM - 1) / BM;
            for (int i = 0; i < ntile; i++) {
                g_tile_e[nt] = e;
                g_tile_r0[nt] = o + i * BM;
                nt++;
            }
            o += ntile * BM;
        }
        g_ntiles = nt;
    }
    __syncthreads();
    for (int p = t; p < PAIRS; p += blockDim.x) {
        int e = idx64 ? (int)((const long long*)idxp)[p] : ((const int*)idxp)[p];
        int r = off[e] + atomicAdd(&cur[e], 1);
        g_row_token[r] = p >> 1;
        g_row_rw[r] = rw[p];
        g_rowof[p] = r;
    }
}

// ---------------- fp16 conversion prepass (4 float -> 4 half per thread) --------
__global__ void convert_kernel(const float* __restrict__ src, __half* __restrict__ dst) {
    size_t i = (size_t)blockIdx.x * blockDim.x + threadIdx.x;
    float4 v = ((const float4*)src)[i];
    __half2* d = (__half2*)dst + 2 * i;
    d[0] = __floats2half2_rn(v.x, v.y);
    d[1] = __floats2half2_rn(v.z, v.w);
}

// ---------------- fp16 tensor-core GEMM (shared core) ---------------------------
// G1: h1h = half(silu(gather(xh) @ w1[e])), K=HIDDEN, B row-len FFN
// G2: y   = (h1h @ w2[e]) * rw,             K=FFN,    B row-len HIDDEN
template <int IS_G2>
__global__ __launch_bounds__(256, 1) void gemm_kernel() {
    int mt = blockIdx.x;
    if (mt >= g_ntiles) return;
    const __half* w = IS_G2 ? (g_sel_w1 ? g_wh1 : g_wh0) : (g_sel_w1 ? g_wh0 : g_wh1);
    const int K  = IS_G2 ? FFN : HIDDEN;
    const int LD = IS_G2 ? HIDDEN : FFN;
    int e  = g_tile_e[mt];
    int r0 = g_tile_r0[mt];
    int n0 = blockIdx.y * BN;

    extern __shared__ __align__(16) char smem[];
    uint32_t sb = (uint32_t)__cvta_generic_to_shared(smem);
    int t = threadIdx.x;
    int lane = t & 31, warp = t >> 5;

    int*   stok = (int*)(smem + SMETA);
    float* srw  = (float*)(smem + SMETA);
    if (IS_G2) { for (int i = t; i < BM; i += 256) srw[i] = g_row_rw[r0 + i]; }
    else       { for (int i = t; i < BM; i += 256) stok[i] = g_row_token[r0 + i]; }
    __syncthreads();

    int wm = warp >> 2, wn = warp & 3;   // 2x4 warps; warp tile 64x64
    int g = lane >> 2, tg = lane & 3;
    int l15 = lane & 15, lhi = lane >> 4;

    // ldmatrix per-lane base offsets (bytes within a stage)
    uint32_t aoff = (uint32_t)((wm * 64 + l15) * AS_STRIDE + lhi * 16);
    uint32_t boff = (uint32_t)(l15 * BS_STRIDE + (wn * 64 + lhi * 8) * 2);

    // cp.async coords: A 512 chunks (2/thread), B 1024 chunks (4/thread)
    int a_row[2]; uint32_t aDst[2]; const __half* aSrc[2]; bool aVal[2];
#pragma unroll
    for (int j = 0; j < 2; j++) {
        int q = t + j * 256;
        a_row[j] = q >> 2;
        int cc = q & 3;
        aDst[j] = sb + SA + a_row[j] * AS_STRIDE + cc * 16;
        if (IS_G2) {
            aSrc[j] = g_h1h + (size_t)(r0 + a_row[j]) * FFN + cc * 8;
            aVal[j] = true;
        } else {
            int tok = stok[a_row[j]];
            aSrc[j] = g_xh + (size_t)(tok < 0 ? 0 : tok) * HIDDEN + cc * 8;
            aVal[j] = (tok >= 0);
        }
    }
    const __half* wE = w + (size_t)e * HIDDEN * FFN + n0;
    int b_k[4]; uint32_t bDst[4]; int b_cc[4];
#pragma unroll
    for (int j = 0; j < 4; j++) {
        int q = t + j * 256;
        b_k[j]  = q >> 5;
        b_cc[j] = q & 31;
        bDst[j] = sb + SB + b_k[j] * BS_STRIDE + b_cc[j] * 16;
    }

    float acc[4][8][4];
#pragma unroll
    for (int mi = 0; mi < 4; mi++)
#pragma unroll
        for (int ni = 0; ni < 8; ni++)
#pragma unroll
            for (int c = 0; c < 4; c++) acc[mi][ni][c] = 0.0f;

    // prologue: stage 0 <- k0=0
#pragma unroll
    for (int j = 0; j < 2; j++) cp16s(aDst[j], aSrc[j], aVal[j]);
#pragma unroll
    for (int j = 0; j < 4; j++)
        cp16s(bDst[j], wE + (size_t)b_k[j] * LD + b_cc[j] * 8, true);
    cp_commit();

    const int NSLAB = K / BK;
    for (int slab = 0; slab < NSLAB; slab++) {
        int s = slab & 1;
        int k1 = (slab + 1) * BK;
        if (k1 < K) {
            int sn = s ^ 1;
#pragma unroll
            for (int j = 0; j < 2; j++)
                cp16s(aDst[j] + sn * SA_STAGE - s * 0 + (sn ? SA_STAGE : 0) * 0, aSrc[j] + k1, aVal[j]);
            // (address arithmetic explicit below instead)
        }
        // NOTE: compute explicit stage addresses (above no-op kept minimal):
        if (k1 < K) {
            int sn = s ^ 1;
#pragma unroll
            for (int j = 0; j < 2; j++)
                cp16s(sb + SA + sn * SA_STAGE + a_row[j] * AS_STRIDE + ((t + j * 256) & 3) * 16,
                      aSrc[j] + k1, aVal[j]);
#pragma unroll
            for (int j = 0; j < 4; j++)
                cp16s(sb + SB + sn * SB_STAGE + b_k[j] * BS_STRIDE + b_cc[j] * 16,
                      wE + (size_t)(k1 + b_k[j]) * LD + b_cc[j] * 8, true);
        }
        cp_commit();
        cp_wait1();
        __syncthreads();

        uint32_t aBase = sb + SA + s * SA_STAGE + aoff;
        uint32_t bBase = sb + SB + s * SB_STAGE + boff;
#pragma unroll
        for (int kk = 0; kk < BK; kk += 16) {
            uint32_t a[4][4], b[8][2];
#pragma unroll
            for (int mi = 0; mi < 4; mi++)
                ldsm_x4(a[mi][0], a[mi][1], a[mi][2], a[mi][3],
                        aBase + mi * 16 * AS_STRIDE + kk * 2);
#pragma unroll
            for (int p = 0; p < 4; p++)
                ldsm_x4t(b[2 * p][0], b[2 * p][1], b[2 * p + 1][0], b[2 * p + 1][1],
                         bBase + kk * BS_STRIDE + p * 32);
#pragma unroll
            for (int mi = 0; mi < 4; mi++)
#pragma unroll
                for (int ni = 0; ni < 8; ni++)
                    mma_f16(acc[mi][ni], a[mi][0], a[mi][1], a[mi][2], a[mi][3],
                            b[ni][0], b[ni][1]);
        }
        __syncthreads();
    }

    // epilogue
#pragma unroll
    for (int mi = 0; mi < 4; mi++) {
        int lr = wm * 64 + mi * 16 + g;
        if (IS_G2) {
            float w0 = srw[lr];
            float w1r = srw[lr + 8];
#pragma unroll
            for (int ni = 0; ni < 8; ni++) {
                int r = r0 + lr;
                int c = n0 + wn * 64 + ni * 8 + 2 * tg;
                *(float2*)(g_y + (size_t)r * HIDDEN + c) =
                    make_float2(acc[mi][ni][0] * w0, acc[mi][ni][1] * w0);
                *(float2*)(g_y + (size_t)(r + 8) * HIDDEN + c) =
                    make_float2(acc[mi][ni][2] * w1r, acc[mi][ni][3] * w1r);
            }
        } else {
#pragma unroll
            for (int ni = 0; ni < 8; ni++) {
                int r = r0 + lr;
                int c = n0 + wn * 64 + ni * 8 + 2 * tg;
                *(__half2*)(g_h1h + (size_t)r * FFN + c) =
                    __floats2half2_rn(silu(acc[mi][ni][0]), silu(acc[mi][ni][1]));
                *(__half2*)(g_h1h + (size_t)(r + 8) * FFN + c) =
                    __floats2half2_rn(silu(acc[mi][ni][2]), silu(acc[mi][ni][3]));
            }
        }
    }
}

// ---------------- combine: out[b] = y[row(b,0)] + y[row(b,1)] ----------------
__global__ void combine_kernel(float* __restrict__ out) {
    int b = blockIdx.x;
    int t = threadIdx.x;
    int r0 = g_rowof[2 * b];
    int r1 = g_rowof[2 * b + 1];
    float4 v0 = *(const float4*)(g_y + (size_t)r0 * HIDDEN + t * 4);
    float4 v1 = *(const float4*)(g_y + (size_t)r1 * HIDDEN + t * 4);
    float4 o;
    o.x = v0.x + v1.x; o.y = v0.y + v1.y; o.z = v0.z + v1.z; o.w = v0.w + v1.w;
    *(float4*)(out + (size_t)b * HIDDEN + t * 4) = o;
}

// ---------------- launch ----------------
extern "C" void kernel_launch(void* const* d_in, const int* in_sizes, int n_in,
                              void* d_out, int out_size) {
    const float* x = nullptr;
    const float* big[2] = {nullptr, nullptr};
    const void*  sm[2]  = {nullptr, nullptr};
    int nb = 0, ns = 0;
    for (int i = 0; i < n_in; i++) {
        long long sz = in_sizes[i];
        if (sz == (long long)BATCH * HIDDEN) {
            x = (const float*)d_in[i];
        } else if (sz == (long long)NUM_EXPERTS * HIDDEN * FFN) {
            if (nb < 2) big[nb++] = (const float*)d_in[i];
        } else if (sz == (long long)PAIRS) {
            if (ns < 2) sm[ns++] = d_in[i];
        }
    }
    float* out = (float*)d_out;
    if (!x || nb != 2 || ns != 2) return;

    cudaFuncSetAttribute(gemm_kernel<0>, cudaFuncAttributeMaxDynamicSharedMemorySize, SMEM_BYTES);
    cudaFuncSetAttribute(gemm_kernel<1>, cudaFuncAttributeMaxDynamicSharedMemorySize, SMEM_BYTES);

    __half* wh0 = nullptr; __half* wh1 = nullptr; __half* xh = nullptr;
    cudaGetSymbolAddress((void**)&wh0, g_wh0);
    cudaGetSymbolAddress((void**)&wh1, g_wh1);
    cudaGetSymbolAddress((void**)&xh,  g_xh);

    route_kernel<<<1, 256>>>(sm[0], sm[1], big[0], big[1]);
    convert_kernel<<<(NUM_EXPERTS * HIDDEN * FFN / 4) / 256, 256>>>(big[0], wh0);
    convert_kernel<<<(NUM_EXPERTS * HIDDEN * FFN / 4) / 256, 256>>>(big[1], wh1);
    convert_kernel<<<(BATCH * HIDDEN / 4) / 256, 256>>>(x, xh);
    gemm_kernel<0><<<dim3(MAX_MT, FFN / BN), 256, SMEM_BYTES>>>();
    gemm_kernel<1><<<dim3(MAX_MT, HIDDEN / BN), 256, SMEM_BYTES>>>();
    combine_kernel<<<BATCH, 256>>>(out);
}